// round 6
// baseline (speedup 1.0000x reference)
#include <cuda_runtime.h>
#include <cuda_bf16.h>

// Problem constants
#define BB 4
#define CC 3
#define HW 45056          // 256*176
#define SS 5
#define MM 18
#define SMN (SS*MM)       // 90
#define TILE 1024         // scalars per hw tile
#define NT4 (TILE/4)      // 256 float4 per tile per channel
#define NTILES (HW/TILE)  // 44
#define NGROUP 3
#define SMG (SMN/NGROUP)  // 30
#define NCOMP 16          // 1 mask sum + 3 channels * 5 moments

#define K1C 0.0001f       // (0.01)^2
#define K2C 0.0009f       // (0.03)^2
#define EPSF 1e-6f

// zero-initialized at module load; finalize_kernel re-zeroes it after use so
// every kernel_launch invocation (and graph replay) starts from zeros.
__device__ float g_part[BB * SMN * NCOMP];

// ---------- f32x2 packed math helpers (sm_103a) ----------
__device__ __forceinline__ unsigned long long pk2(float lo, float hi) {
    unsigned long long r;
    asm("mov.b64 %0, {%1, %2};" : "=l"(r) : "f"(lo), "f"(hi));
    return r;
}
__device__ __forceinline__ void upk2(unsigned long long v, float& lo, float& hi) {
    asm("mov.b64 {%0, %1}, %2;" : "=f"(lo), "=f"(hi) : "l"(v));
}
__device__ __forceinline__ unsigned long long mul2(unsigned long long a, unsigned long long b) {
    unsigned long long r;
    asm("mul.rn.f32x2 %0, %1, %2;" : "=l"(r) : "l"(a), "l"(b));
    return r;
}
__device__ __forceinline__ unsigned long long add2(unsigned long long a, unsigned long long b) {
    unsigned long long r;
    asm("add.rn.f32x2 %0, %1, %2;" : "=l"(r) : "l"(a), "l"(b));
    return r;
}
__device__ __forceinline__ unsigned long long fma2(unsigned long long a, unsigned long long b,
                                                   unsigned long long c) {
    unsigned long long r;
    asm("fma.rn.f32x2 %0, %1, %2, %3;" : "=l"(r) : "l"(a), "l"(b), "l"(c));
    return r;
}

// ---------- kernel 1: masked moments ----------
// grid: (NTILES, BB, NGROUP), block: 256, >=2 blocks/SM (regs capped at 128)
__global__ void __launch_bounds__(256, 2)
moments_kernel(const float* __restrict__ X,
               const float* __restrict__ Y,
               const float* __restrict__ Mk) {
    __shared__ __align__(16) float tile[6 * TILE];  // [0..2]=X' channels, [3..5]=Y'

    const int b    = blockIdx.y;
    const int t0   = blockIdx.x * TILE;
    const int g    = blockIdx.z;
    const int tid  = threadIdx.x;
    const int warp = tid >> 5;
    const int lane = tid & 31;

    // --- fill tile with rescaled X', Y' (float4 path, 6 iters x 256 threads) ---
    const float4* X4 = (const float4*)X;
    const float4* Y4 = (const float4*)Y;
    float4 vbuf[6];
    #pragma unroll
    for (int ch = 0; ch < 3; ch++) {
        vbuf[ch]     = X4[((b * 3 + ch) * HW + t0) / 4 + tid];
        vbuf[ch + 3] = Y4[((b * 3 + ch) * HW + t0) / 4 + tid];
    }
    #pragma unroll
    for (int ch = 0; ch < 6; ch++) {
        float4 v = vbuf[ch];
        v.x = fmaf(v.x, 0.5f, 0.5f);
        v.y = fmaf(v.y, 0.5f, 0.5f);
        v.z = fmaf(v.z, 0.5f, 0.5f);
        v.w = fmaf(v.w, 0.5f, 0.5f);
        *(float4*)&tile[ch * TILE + tid * 4] = v;
    }
    __syncthreads();

    // --- each warp owns (s,m) tasks within this block's group ---
    for (int sm = g * SMG + warp; sm < (g + 1) * SMG; sm += 8) {
        const float4* M4 =
            (const float4*)(Mk + (size_t)(b * SMN + sm) * (size_t)HW + t0);

        // Front-batched mask loads: 8 independent LDG.128 in flight per warp.
        float4 mbuf[NT4 / 32];
        #pragma unroll
        for (int i = 0; i < NT4 / 32; i++)
            mbuf[i] = __ldcs(&M4[i * 32 + lane]);   // streaming: evict-first

        // acc[0]=mask sum; acc[1+c*5+{0..4}] = {mx, my, mxx, myy, mxy} per channel
        unsigned long long acc[NCOMP];
        #pragma unroll
        for (int k = 0; k < NCOMP; k++) acc[k] = 0ULL;  // (0.f,0.f)

        #pragma unroll
        for (int i = 0; i < NT4 / 32; i++) {
            float4 m = mbuf[i];
            unsigned long long m01 = pk2(m.x, m.y);
            unsigned long long m23 = pk2(m.z, m.w);
            acc[0] = add2(acc[0], m01);
            acc[0] = add2(acc[0], m23);

            #pragma unroll
            for (int c = 0; c < 3; c++) {
                float4 x = *(const float4*)&tile[c * TILE + (i * 32 + lane) * 4];
                float4 y = *(const float4*)&tile[(3 + c) * TILE + (i * 32 + lane) * 4];
                unsigned long long x01 = pk2(x.x, x.y), x23 = pk2(x.z, x.w);
                unsigned long long y01 = pk2(y.x, y.y), y23 = pk2(y.z, y.w);

                unsigned long long mx01 = mul2(m01, x01);
                unsigned long long my01 = mul2(m01, y01);
                unsigned long long mx23 = mul2(m23, x23);
                unsigned long long my23 = mul2(m23, y23);

                const int o = 1 + c * 5;
                acc[o + 0] = add2(acc[o + 0], mx01);
                acc[o + 0] = add2(acc[o + 0], mx23);
                acc[o + 1] = add2(acc[o + 1], my01);
                acc[o + 1] = add2(acc[o + 1], my23);
                acc[o + 2] = fma2(mx01, x01, acc[o + 2]);
                acc[o + 2] = fma2(mx23, x23, acc[o + 2]);
                acc[o + 3] = fma2(my01, y01, acc[o + 3]);
                acc[o + 3] = fma2(my23, y23, acc[o + 3]);
                acc[o + 4] = fma2(mx01, y01, acc[o + 4]);
                acc[o + 4] = fma2(mx23, y23, acc[o + 4]);
            }
        }

        // collapse f32x2 halves, butterfly reduce across warp
        float v[NCOMP];
        #pragma unroll
        for (int k = 0; k < NCOMP; k++) {
            float lo, hi;
            upk2(acc[k], lo, hi);
            v[k] = lo + hi;
        }
        #pragma unroll
        for (int off = 16; off > 0; off >>= 1) {
            #pragma unroll
            for (int k = 0; k < NCOMP; k++)
                v[k] += __shfl_xor_sync(0xffffffffu, v[k], off);
        }
        if (lane == 0) {
            float* p = &g_part[(b * SMN + sm) * NCOMP];
            #pragma unroll
            for (int k = 0; k < NCOMP; k++) atomicAdd(p + k, v[k]);
        }
    }
}

// ---------- kernel 2: SSIM algebra + final reduction + re-zero partials ----------
__global__ void finalize_kernel(float* __restrict__ out) {
    __shared__ float csb[BB * SS];
    __shared__ float ssb[BB * SS];
    int tid = threadIdx.x;
    if (tid < BB * SS) { csb[tid] = 0.0f; ssb[tid] = 0.0f; }
    __syncthreads();

    for (int idx = tid; idx < BB * SMN * CC; idx += blockDim.x) {
        int b  = idx / (SMN * CC);
        int r  = idx % (SMN * CC);
        int s  = r / (MM * CC);
        int mc = r % (MM * CC);
        int m  = mc / CC;
        int c  = mc % CC;
        const float* p = &g_part[(b * SMN + s * MM + m) * NCOMP];
        float inv  = 1.0f / (p[0] + EPSF);
        float mu1  = p[1 + c * 5 + 0] * inv;
        float mu2  = p[1 + c * 5 + 1] * inv;
        float mu11 = p[1 + c * 5 + 2] * inv;
        float mu22 = p[1 + c * 5 + 3] * inv;
        float mu12 = p[1 + c * 5 + 4] * inv;
        float s1  = mu11 - mu1 * mu1;
        float s2  = mu22 - mu2 * mu2;
        float s12 = mu12 - mu1 * mu2;
        float cs   = (2.0f * s12 + K2C) / (s1 + s2 + K2C);
        float ssim = (2.0f * mu1 * mu2 + K1C) / (mu1 * mu1 + mu2 * mu2 + K1C) * cs;
        cs   = fmaxf(cs, 0.0f);
        ssim = fmaxf(ssim, 0.0f);
        atomicAdd(&csb[b * SS + s], cs);
        atomicAdd(&ssb[b * SS + s], ssim);
    }
    __syncthreads();

    // re-zero partials for the next invocation / graph replay
    for (int i = tid; i < BB * SMN * NCOMP; i += blockDim.x) g_part[i] = 0.0f;
    __syncthreads();

    if (tid == 0) {
        const float invMC = 1.0f / (float)(MM * CC);
        float accb = 0.0f;
        for (int b = 0; b < BB; b++) {
            float prod = ssb[b * SS + (SS - 1)] * invMC;
            for (int s = 0; s < SS - 1; s++) prod *= csb[b * SS + s] * invMC;
            accb += prod;
        }
        out[0] = accb / (float)BB;
    }
}

extern "C" void kernel_launch(void* const* d_in, const int* in_sizes, int n_in,
                              void* d_out, int out_size) {
    const float* X  = (const float*)d_in[0];
    const float* Y  = (const float*)d_in[1];
    const float* Mk = (const float*)d_in[2];
    float* out = (float*)d_out;

    dim3 grid(NTILES, BB, NGROUP);
    moments_kernel<<<grid, 256>>>(X, Y, Mk);
    finalize_kernel<<<1, 256>>>(out);
}